// round 6
// baseline (speedup 1.0000x reference)
#include <cuda_runtime.h>
#include <cstdint>

#define BATCH   8
#define NPTS    8192
#define DIM     64
#define SPTS    1024      // NPOINT
#define NS      32        // NSAMPLE
#define MROWS   (BATCH*SPTS*NS)   // 262144
#define NBLK    (MROWS/64)        // 4096 gemm blocks

typedef unsigned long long u64;

// ---------------- f32x2 packed helpers --------------------------------------
__device__ __forceinline__ u64 pack2(float lo, float hi){
  u64 r; asm("mov.b64 %0,{%1,%2};" : "=l"(r) : "f"(lo), "f"(hi)); return r;
}
__device__ __forceinline__ void unpack2(float& lo, float& hi, u64 p){
  asm("mov.b64 {%0,%1},%2;" : "=f"(lo), "=f"(hi) : "l"(p));
}
__device__ __forceinline__ u64 add2(u64 a, u64 b){
  u64 r; asm("add.rn.f32x2 %0,%1,%2;" : "=l"(r) : "l"(a), "l"(b)); return r;
}
__device__ __forceinline__ u64 mul2(u64 a, u64 b){
  u64 r; asm("mul.rn.f32x2 %0,%1,%2;" : "=l"(r) : "l"(a), "l"(b)); return r;
}
__device__ __forceinline__ void fma2(u64& d, u64 a, u64 b){
  asm("fma.rn.f32x2 %0,%1,%2,%0;" : "+l"(d) : "l"(a), "l"(b));
}

// ---------------- scratch ---------------------------------------------------
__device__ int   g_fps_idx[BATCH*SPTS];
__device__ float g_new_xyz[BATCH*SPTS*3];
__device__ int   g_ball[BATCH*SPTS*NS];
__device__ float g_ptsT[BATCH*NPTS*DIM];
__device__ float g_h1[(size_t)MROWS*64];
__device__ float g_h2[(size_t)MROWS*64];
__device__ float g_mx[(size_t)BATCH*SPTS*128];
__device__ float g_mn[(size_t)BATCH*SPTS*128];
__device__ float g_pS [(size_t)128*NBLK];   // channel-major
__device__ float g_pSS[(size_t)128*NBLK];
__device__ float g_scale[128];
__device__ float g_shift[128];

// ---------------- FPS: value phase + guarded index phase --------------------
__global__ __launch_bounds__(1024,1) void fps_kernel(const float* __restrict__ xyz){
  extern __shared__ float sxyz[];            // 3*8192 floats
  __shared__ float swarp[32];
  __shared__ float svmax;
  __shared__ unsigned srev[2];
  const int b   = blockIdx.x;
  const int tid = threadIdx.x;
  const float* xb = xyz + (size_t)b*3*NPTS;
  for (int i=tid; i<3*NPTS; i+=1024) sxyz[i]=xb[i];
  if (tid<2) srev[tid]=0u;
  __syncthreads();

  u64 rx2[4], ry2[4], rz2[4];
  float rdl[4], rdh[4];
#pragma unroll
  for (int j=0;j<4;j++){
    int plo=j*1024+tid, phi=(j+4)*1024+tid;
    rx2[j]=pack2(sxyz[plo],       sxyz[phi]);
    ry2[j]=pack2(sxyz[NPTS+plo],  sxyz[NPTS+phi]);
    rz2[j]=pack2(sxyz[2*NPTS+plo],sxyz[2*NPTS+phi]);
    rdl[j]=1e10f; rdh[j]=1e10f;
  }
  int far=0, p=0;
  const int lane=tid&31, wid=tid>>5;
  const unsigned base = (unsigned)(NPTS-1-tid);

  for (int it=0; it<SPTS; ++it){
    if (tid==0) g_fps_idx[b*SPTS+it]=far;
    const float cx=sxyz[far], cy=sxyz[NPTS+far], cz=sxyz[2*NPTS+far];
    const u64 ncx=pack2(-cx,-cx), ncy=pack2(-cy,-cy), ncz=pack2(-cz,-cz);
    float m=0.f;
#pragma unroll
    for (int j=0;j<4;j++){
      u64 dx=add2(rx2[j],ncx);            // x + (-c) == x - c (IEEE)
      u64 dy=add2(ry2[j],ncy);
      u64 dz=add2(rz2[j],ncz);
      u64 s2=add2(add2(mul2(dx,dx),mul2(dy,dy)),mul2(dz,dz));
      float dl,dh; unpack2(dl,dh,s2);
      float nl=fminf(rdl[j],dl), nh=fminf(rdh[j],dh);
      rdl[j]=nl; rdh[j]=nh;
      m = fmaxf(m, fmaxf(nl,nh));
    }
#pragma unroll
    for (int o=16;o>0;o>>=1)
      m = fmaxf(m, __shfl_xor_sync(0xffffffffu,m,o));
    if (lane==0) swarp[wid]=m;
    __syncthreads();                       // (1) warp maxima ready
    if (wid==0){
      float v=swarp[lane];
#pragma unroll
      for (int o=16;o>0;o>>=1)
        v = fmaxf(v, __shfl_xor_sync(0xffffffffu,v,o));
      if (lane==0) svmax=v;
    }
    __syncthreads();                       // (2) block max ready
    const float vmax = svmax;
    if (m==vmax){                          // warp-uniform: only matching warps
      unsigned rev=0u;
#pragma unroll
      for (int j=0;j<4;j++){
        if (rdl[j]==vmax){ unsigned r=base-(unsigned)(j<<10);     rev = r>rev?r:rev; }
        if (rdh[j]==vmax){ unsigned r=base-(unsigned)((j+4)<<10); rev = r>rev?r:rev; }
      }
#pragma unroll
      for (int o=16;o>0;o>>=1){
        unsigned r2=__shfl_xor_sync(0xffffffffu,rev,o);
        rev = r2>rev?r2:rev;
      }
      if (lane==0 && rev) atomicMax(&srev[p], rev);
    }
    __syncthreads();                       // (3) index ready
    far = (NPTS-1) - (int)srev[p];         // srev==0 => point 8191 (consistent)
    if (tid==0) srev[p^1]=0u;
    p ^= 1;
  }
}

// ---------------- new_xyz gather + first output section --------------------
__global__ void newxyz_kernel(const float* __restrict__ xyz, float* __restrict__ out){
  int b=blockIdx.x, s=threadIdx.x;
  int idx = g_fps_idx[b*SPTS+s];
#pragma unroll
  for (int d=0; d<3; d++){
    float v = xyz[(size_t)b*3*NPTS + (size_t)d*NPTS + idx];
    g_new_xyz[(b*SPTS+s)*3+d]=v;
    out[(size_t)b*3*SPTS + (size_t)d*SPTS + s]=v;
  }
}

// ---------------- ball query: one warp per query ---------------------------
__global__ void ball_kernel(const float* __restrict__ xyz){
  const int gw   = (blockIdx.x*blockDim.x + threadIdx.x) >> 5;  // 0..8191
  const int lane = threadIdx.x & 31;
  const int wl   = threadIdx.x >> 5;
  const int b = gw >> 10;
  __shared__ int sidx[8][NS];
  const float cx=g_new_xyz[gw*3+0], cy=g_new_xyz[gw*3+1], cz=g_new_xyz[gw*3+2];
  const float* xb = xyz + (size_t)b*3*NPTS;
  unsigned cnt=0;
  for (int basep=0; basep<NPTS; basep+=32){
    int pp = basep+lane;
    float dx=__fsub_rn(cx,xb[pp]);
    float dy=__fsub_rn(cy,xb[NPTS+pp]);
    float dz=__fsub_rn(cz,xb[2*NPTS+pp]);
    float d=__fadd_rn(__fadd_rn(__fmul_rn(dx,dx),__fmul_rn(dy,dy)),__fmul_rn(dz,dz));
    bool in = !(d > 0.04f);
    unsigned mm = __ballot_sync(0xffffffffu, in);
    if (in){
      unsigned r = cnt + __popc(mm & ((1u<<lane)-1u));
      if (r < NS) sidx[wl][r] = pp;
    }
    cnt += __popc(mm);
    if (cnt >= NS) break;
  }
  __syncwarp();
  unsigned c = cnt < NS ? cnt : NS;
  int first = sidx[wl][0];
  int v = (lane < (int)c) ? sidx[wl][lane] : first;
  g_ball[gw*NS + lane] = v;
}

// ---------------- points transpose (B,64,N) -> (B,N,64) --------------------
__global__ void transpose_kernel(const float* __restrict__ pts){
  __shared__ float tile[32][33];
  int b  = blockIdx.z;
  int n0 = blockIdx.x*32;
  int c0 = blockIdx.y*32;
  int tx = threadIdx.x, ty = threadIdx.y;     // 32 x 8
  const float* pb = pts + (size_t)b*DIM*NPTS;
#pragma unroll
  for (int j=0;j<32;j+=8)
    tile[ty+j][tx] = pb[(size_t)(c0+ty+j)*NPTS + n0+tx];
  __syncthreads();
  float* ob = g_ptsT + (size_t)b*NPTS*DIM;
#pragma unroll
  for (int j=0;j<32;j+=8)
    ob[(size_t)(n0+ty+j)*DIM + c0+tx] = tile[tx][ty+j];
}

// ---------------- GEMM: even/odd-k f32x2, interleaved row/col ownership -----
// MODE 0: layer1 (gather A from ptsT/ball, feature order [pts64|xyz3|0], K=68)
// MODE 1: layer2 (A = prev H with fused BN+ReLU, K=64)
// MODE 2: layer3 (as MODE1 + max/min pool epilogue, no H store)
// Thread owns rows {tm,tm+16,tm+32,tm+48}, cols {tn+j*CS}.
template<int K, int BN, int T, int MODE>
__global__ __launch_bounds__(T) void gemm_kernel(
    const float* __restrict__ A, const float* __restrict__ W,
    const float* __restrict__ bias, float* __restrict__ H,
    const float* __restrict__ xyz){
  constexpr bool GATHER = (MODE==0);
  constexpr bool AFF    = (MODE>=1);
  constexpr bool POOL   = (MODE==2);
  constexpr int  CS = BN/4;             // col spacing (16 or 32)
  constexpr int  TN = T/16;             // tn range  (== CS)
  extern __shared__ float sm[];
  float* sA    = sm;                    // [64][68] m-major
  float* sB    = sA + 64*68;            // [BN][68] n-major
  float* sbias = sB + BN*68;            // BN
  float* ssc   = sbias + BN;            // 64 (AFF)
  float* ssh   = ssc + 64;
  __shared__ int   sn[64];
  __shared__ float sctr[6];
  const int tid = threadIdx.x;
  const int m0  = blockIdx.x*64;

  // ---- B tile (W cols permuted for GATHER feature order) ----
  for (int idx=tid; idx<BN*68; idx+=T){
    int n=idx/68, c=idx-n*68;
    float v;
    if (GATHER) v = (c<64)? W[n*67 + c+3] : (c<67 ? W[n*67 + (c-64)] : 0.f);
    else        v = (c<64)? W[n*64 + c] : 0.f;
    sB[idx]=v;
  }
  for (int o=tid;o<BN;o+=T) sbias[o]=bias[o];
  if (AFF) for (int c=tid;c<64;c+=T){ ssc[c]=g_scale[c]; ssh[c]=g_shift[c]; }

  if (GATHER){
    if (tid<64) sn[tid] = g_ball[(size_t)m0 + tid];
    if (tid>=64 && tid<70) sctr[tid-64] = g_new_xyz[(m0>>5)*3 + (tid-64)];
    __syncthreads();
    const int m = tid>>2, g = tid&3;
    const int b = m0 >> 15;             // 32768 rows per batch
    const int n = sn[m];
    const float4* pr = (const float4*)(g_ptsT + ((size_t)b*NPTS + n)*DIM);
    float4* ar = (float4*)(sA + m*68);
#pragma unroll
    for (int q=g; q<16; q+=4) ar[q] = pr[q];
    if (g==0){
      const float* xb = xyz + (size_t)b*3*NPTS;
      const int grp = (m>>5)*3;
      sA[m*68+64] = __fsub_rn(xb[n],        sctr[grp+0]);
      sA[m*68+65] = __fsub_rn(xb[NPTS+n],   sctr[grp+1]);
      sA[m*68+66] = __fsub_rn(xb[2*NPTS+n], sctr[grp+2]);
      sA[m*68+67] = 0.f;
    }
  } else {
    __syncthreads();                    // ssc/ssh ready
    const float4* A4 = (const float4*)A;
    for (int idx=tid; idx<64*16; idx+=T){
      int m=idx>>4, c4=idx&15;
      float4 v = A4[(size_t)(m0+m)*16 + c4];
      int cc=c4*4;
      v.x = fmaxf(fmaf(v.x, ssc[cc  ], ssh[cc  ]), 0.f);
      v.y = fmaxf(fmaf(v.y, ssc[cc+1], ssh[cc+1]), 0.f);
      v.z = fmaxf(fmaf(v.z, ssc[cc+2], ssh[cc+2]), 0.f);
      v.w = fmaxf(fmaf(v.w, ssc[cc+3], ssh[cc+3]), 0.f);
      *(float4*)&sA[m*68+cc] = v;
    }
  }
  __syncthreads();

  // ---- main loop: zero splats, conflict-free LDS ----
  const int tm = tid/TN, tn = tid%TN;
  u64 acc[4][4];
#pragma unroll
  for (int i=0;i<4;i++)
#pragma unroll
    for (int j=0;j<4;j++) acc[i][j]=0ull;

#pragma unroll 4
  for (int k=0;k<K;k+=4){
    float4 av[4], bv[4];
#pragma unroll
    for (int i=0;i<4;i++) av[i] = *(const float4*)(sA + (tm+i*16)*68 + k);
#pragma unroll
    for (int j=0;j<4;j++) bv[j] = *(const float4*)(sB + (tn+j*CS)*68 + k);
#pragma unroll
    for (int i=0;i<4;i++){
      u64 a01=((const u64*)&av[i])[0], a23=((const u64*)&av[i])[1];
#pragma unroll
      for (int j=0;j<4;j++){
        fma2(acc[i][j], a01, ((const u64*)&bv[j])[0]);
        fma2(acc[i][j], a23, ((const u64*)&bv[j])[1]);
      }
    }
  }

  float vals[4][4];
#pragma unroll
  for (int i=0;i<4;i++)
#pragma unroll
    for (int j=0;j<4;j++){
      float lo,hi; unpack2(lo,hi,acc[i][j]);
      vals[i][j] = (lo+hi) + sbias[tn+j*CS];
    }

  if (!POOL){
#pragma unroll
    for (int i=0;i<4;i++)
#pragma unroll
      for (int j=0;j<4;j++)
        H[(size_t)(m0+tm+i*16)*BN + tn + j*CS] = vals[i][j];
  }

  // ---- stats epilogue (reuses sA region; stride 17 = conflict-free) ----
  __syncthreads();
  float* sS  = sm;                      // [BN][17]
  float* sSS = sm + BN*17;
#pragma unroll
  for (int j=0;j<4;j++){
    int col = tn + j*CS;
    float v0=vals[0][j], v1=vals[1][j], v2=vals[2][j], v3=vals[3][j];
    sS [col*17+tm] = ((v0+v1)+v2)+v3;
    sSS[col*17+tm] = ((v0*v0+v1*v1)+v2*v2)+v3*v3;
  }
  __syncthreads();
  if (tid < BN){
    float s=0.f, ss=0.f;
#pragma unroll
    for (int t=0;t<16;t++){ s+=sS[tid*17+t]; ss+=sSS[tid*17+t]; }
    g_pS [(size_t)tid*NBLK + blockIdx.x] = s;
    g_pSS[(size_t)tid*NBLK + blockIdx.x] = ss;
  }

  if (POOL){
    // rows i=0,1 -> sample group 0 ; i=2,3 -> group 1
#pragma unroll
    for (int grp=0; grp<2; grp++){
      __syncthreads();
#pragma unroll
      for (int j=0;j<4;j++){
        int col = tn + j*CS;
        sS [col*17+tm] = fmaxf(vals[2*grp][j], vals[2*grp+1][j]);
        sSS[col*17+tm] = fminf(vals[2*grp][j], vals[2*grp+1][j]);
      }
      __syncthreads();
      if (tid < BN){
        float mx=-3.4e38f, mn=3.4e38f;
#pragma unroll
        for (int t=0;t<16;t++){ mx=fmaxf(mx,sS[tid*17+t]); mn=fminf(mn,sSS[tid*17+t]); }
        size_t gidx = (size_t)(blockIdx.x*2+grp)*128 + tid;
        g_mx[gidx]=mx; g_mn[gidx]=mn;
      }
    }
  }
}

// ---------------- BN stats: one block per channel ---------------------------
__global__ void bnstats_kernel(const float* __restrict__ g, const float* __restrict__ beta){
  __shared__ float sh[512];
  const int c=blockIdx.x, t=threadIdx.x;   // 256 threads
  float s=0.f, ss=0.f;
  const float* ps  = g_pS  + (size_t)c*NBLK;
  const float* pss = g_pSS + (size_t)c*NBLK;
  for (int i=t;i<NBLK;i+=256){ s+=ps[i]; ss+=pss[i]; }
  sh[t]=s; sh[256+t]=ss; __syncthreads();
  for (int o=128;o>0;o>>=1){
    if (t<o){ sh[t]+=sh[t+o]; sh[256+t]+=sh[256+t+o]; }
    __syncthreads();
  }
  if (t==0){
    const float inv = 1.0f/(float)MROWS;
    float mean = sh[0]*inv;
    float var  = sh[256]*inv - mean*mean;
    float rstd = rsqrtf(var + 1e-5f);
    float sc   = rstd*g[c];
    g_scale[c] = sc;
    g_shift[c] = beta[c] - mean*sc;
  }
}

// ---------------- final pool: norm+relu on pre-reduced max/min -------------
__global__ void pool_kernel(float* __restrict__ out){
  const int gq=blockIdx.x;                   // 0..8191 (b*1024+s)
  const int o =threadIdx.x;                  // 0..127
  const int b=gq>>10, s=gq&1023;
  const float sc=g_scale[o], sh=g_shift[o];
  const float mx=g_mx[(size_t)gq*128+o], mn=g_mn[(size_t)gq*128+o];
  float v = (sc>=0.f)? fmaf(mx,sc,sh) : fmaf(mn,sc,sh);
  out[24576 + (size_t)b*131072 + (size_t)o*1024 + s] = fmaxf(v, 0.f);
}

// ---------------- launch ----------------------------------------------------
extern "C" void kernel_launch(void* const* d_in, const int* in_sizes, int n_in,
                              void* d_out, int out_size){
  (void)in_sizes; (void)n_in; (void)out_size;
  const float* xyz = (const float*)d_in[0];
  const float* pts = (const float*)d_in[1];
  const float* w0  = (const float*)d_in[2];
  const float* b0  = (const float*)d_in[3];
  const float* gg0 = (const float*)d_in[4];
  const float* be0 = (const float*)d_in[5];
  const float* w1  = (const float*)d_in[6];
  const float* b1  = (const float*)d_in[7];
  const float* gg1 = (const float*)d_in[8];
  const float* be1 = (const float*)d_in[9];
  const float* w2  = (const float*)d_in[10];
  const float* b2  = (const float*)d_in[11];
  const float* gg2 = (const float*)d_in[12];
  const float* be2 = (const float*)d_in[13];
  float* out = (float*)d_out;

  // dyn smem (floats): 64*68 + BN*68 + BN (+128 if AFF)
  const int smem1 = (64*68 + 64*68  + 64)*4;        // 35072
  const int smem2 = (64*68 + 64*68  + 64 + 128)*4;  // 35584
  const int smem3 = (64*68 + 128*68 + 128 + 128)*4; // 53248

  cudaFuncSetAttribute(fps_kernel, cudaFuncAttributeMaxDynamicSharedMemorySize, 3*NPTS*4);
  cudaFuncSetAttribute((const void*)gemm_kernel<68,64,256,0>,
                       cudaFuncAttributeMaxDynamicSharedMemorySize, smem1);
  cudaFuncSetAttribute((const void*)gemm_kernel<64,64,256,1>,
                       cudaFuncAttributeMaxDynamicSharedMemorySize, smem2);
  cudaFuncSetAttribute((const void*)gemm_kernel<64,128,512,2>,
                       cudaFuncAttributeMaxDynamicSharedMemorySize, smem3);

  float *pH1,*pH2;
  cudaGetSymbolAddress((void**)&pH1, g_h1);
  cudaGetSymbolAddress((void**)&pH2, g_h2);

  fps_kernel<<<BATCH, 1024, 3*NPTS*4>>>(xyz);
  newxyz_kernel<<<BATCH, SPTS>>>(xyz, out);
  ball_kernel<<<1024, 256>>>(xyz);
  transpose_kernel<<<dim3(NPTS/32, DIM/32, BATCH), dim3(32,8)>>>(pts);

  gemm_kernel<68,64,256,0><<<NBLK, 256, smem1>>>(nullptr, w0, b0, pH1, xyz);
  bnstats_kernel<<<64, 256>>>(gg0, be0);

  gemm_kernel<64,64,256,1><<<NBLK, 256, smem2>>>(pH1, w1, b1, pH2, xyz);
  bnstats_kernel<<<64, 256>>>(gg1, be1);

  gemm_kernel<64,128,512,2><<<NBLK, 512, smem3>>>(pH2, w2, b2, nullptr, xyz);
  bnstats_kernel<<<128, 256>>>(gg2, be2);

  pool_kernel<<<BATCH*SPTS, 128>>>(out);
}

// round 7
// speedup vs baseline: 1.4134x; 1.4134x over previous
#include <cuda_runtime.h>
#include <cstdint>

#define BATCH   8
#define NPTS    8192
#define DIM     64
#define SPTS    1024      // NPOINT
#define NS      32        // NSAMPLE
#define MROWS   (BATCH*SPTS*NS)   // 262144
#define NBLK    (MROWS/64)        // 4096 gemm blocks

typedef unsigned long long u64;

// ---------------- f32x2 packed helpers --------------------------------------
__device__ __forceinline__ u64 pack2(float lo, float hi){
  u64 r; asm("mov.b64 %0,{%1,%2};" : "=l"(r) : "f"(lo), "f"(hi)); return r;
}
__device__ __forceinline__ void unpack2(float& lo, float& hi, u64 p){
  asm("mov.b64 {%0,%1},%2;" : "=f"(lo), "=f"(hi) : "l"(p));
}
__device__ __forceinline__ u64 add2(u64 a, u64 b){
  u64 r; asm("add.rn.f32x2 %0,%1,%2;" : "=l"(r) : "l"(a), "l"(b)); return r;
}
__device__ __forceinline__ u64 mul2(u64 a, u64 b){
  u64 r; asm("mul.rn.f32x2 %0,%1,%2;" : "=l"(r) : "l"(a), "l"(b)); return r;
}
__device__ __forceinline__ void fma2(u64& d, u64 a, u64 b){
  asm("fma.rn.f32x2 %0,%1,%2,%0;" : "+l"(d) : "l"(a), "l"(b));
}

// ---------------- scratch ---------------------------------------------------
__device__ int   g_fps_idx[BATCH*SPTS];
__device__ float g_new_xyz[BATCH*SPTS*3];
__device__ int   g_ball[BATCH*SPTS*NS];
__device__ float g_ptsT[BATCH*NPTS*DIM];
__device__ float g_h1[(size_t)MROWS*64];
__device__ float g_h2[(size_t)MROWS*64];
__device__ float g_mx[(size_t)BATCH*SPTS*128];
__device__ float g_mn[(size_t)BATCH*SPTS*128];
__device__ float g_pS [(size_t)128*NBLK];   // channel-major
__device__ float g_pSS[(size_t)128*NBLK];
__device__ float g_scale[128];
__device__ float g_shift[128];

// ---------------- FPS: value phase + guarded index phase --------------------
__global__ __launch_bounds__(1024,1) void fps_kernel(const float* __restrict__ xyz){
  extern __shared__ float sxyz[];            // 3*8192 floats
  __shared__ float swarp[32];
  __shared__ float svmax;
  __shared__ unsigned srev[2];
  const int b   = blockIdx.x;
  const int tid = threadIdx.x;
  const float* xb = xyz + (size_t)b*3*NPTS;
  for (int i=tid; i<3*NPTS; i+=1024) sxyz[i]=xb[i];
  if (tid<2) srev[tid]=0u;
  __syncthreads();

  u64 rx2[4], ry2[4], rz2[4];
  float rdl[4], rdh[4];
#pragma unroll
  for (int j=0;j<4;j++){
    int plo=j*1024+tid, phi=(j+4)*1024+tid;
    rx2[j]=pack2(sxyz[plo],       sxyz[phi]);
    ry2[j]=pack2(sxyz[NPTS+plo],  sxyz[NPTS+phi]);
    rz2[j]=pack2(sxyz[2*NPTS+plo],sxyz[2*NPTS+phi]);
    rdl[j]=1e10f; rdh[j]=1e10f;
  }
  int far=0, p=0;
  const int lane=tid&31, wid=tid>>5;
  const unsigned base = (unsigned)(NPTS-1-tid);

  for (int it=0; it<SPTS; ++it){
    if (tid==0) g_fps_idx[b*SPTS+it]=far;
    const float cx=sxyz[far], cy=sxyz[NPTS+far], cz=sxyz[2*NPTS+far];
    const u64 ncx=pack2(-cx,-cx), ncy=pack2(-cy,-cy), ncz=pack2(-cz,-cz);
    float m=0.f;
#pragma unroll
    for (int j=0;j<4;j++){
      u64 dx=add2(rx2[j],ncx);            // x + (-c) == x - c (IEEE)
      u64 dy=add2(ry2[j],ncy);
      u64 dz=add2(rz2[j],ncz);
      u64 s2=add2(add2(mul2(dx,dx),mul2(dy,dy)),mul2(dz,dz));
      float dl,dh; unpack2(dl,dh,s2);
      float nl=fminf(rdl[j],dl), nh=fminf(rdh[j],dh);
      rdl[j]=nl; rdh[j]=nh;
      m = fmaxf(m, fmaxf(nl,nh));
    }
#pragma unroll
    for (int o=16;o>0;o>>=1)
      m = fmaxf(m, __shfl_xor_sync(0xffffffffu,m,o));
    if (lane==0) swarp[wid]=m;
    __syncthreads();                       // (1) warp maxima ready
    if (wid==0){
      float v=swarp[lane];
#pragma unroll
      for (int o=16;o>0;o>>=1)
        v = fmaxf(v, __shfl_xor_sync(0xffffffffu,v,o));
      if (lane==0) svmax=v;
    }
    __syncthreads();                       // (2) block max ready
    const float vmax = svmax;
    if (m==vmax){                          // warp-uniform guard
      unsigned rev=0u;
#pragma unroll
      for (int j=0;j<4;j++){
        if (rdl[j]==vmax){ unsigned r=base-(unsigned)(j<<10);     rev = r>rev?r:rev; }
        if (rdh[j]==vmax){ unsigned r=base-(unsigned)((j+4)<<10); rev = r>rev?r:rev; }
      }
#pragma unroll
      for (int o=16;o>0;o>>=1){
        unsigned r2=__shfl_xor_sync(0xffffffffu,rev,o);
        rev = r2>rev?r2:rev;
      }
      if (lane==0 && rev) atomicMax(&srev[p], rev);
    }
    __syncthreads();                       // (3) index ready
    far = (NPTS-1) - (int)srev[p];         // srev==0 => point 8191 (consistent)
    if (tid==0) srev[p^1]=0u;
    p ^= 1;
  }
}

// ---------------- new_xyz gather + first output section --------------------
__global__ void newxyz_kernel(const float* __restrict__ xyz, float* __restrict__ out){
  int b=blockIdx.x, s=threadIdx.x;
  int idx = g_fps_idx[b*SPTS+s];
#pragma unroll
  for (int d=0; d<3; d++){
    float v = xyz[(size_t)b*3*NPTS + (size_t)d*NPTS + idx];
    g_new_xyz[(b*SPTS+s)*3+d]=v;
    out[(size_t)b*3*SPTS + (size_t)d*SPTS + s]=v;
  }
}

// ---------------- ball query: one warp per query ---------------------------
__global__ void ball_kernel(const float* __restrict__ xyz){
  const int gw   = (blockIdx.x*blockDim.x + threadIdx.x) >> 5;  // 0..8191
  const int lane = threadIdx.x & 31;
  const int wl   = threadIdx.x >> 5;
  const int b = gw >> 10;
  __shared__ int sidx[8][NS];
  const float cx=g_new_xyz[gw*3+0], cy=g_new_xyz[gw*3+1], cz=g_new_xyz[gw*3+2];
  const float* xb = xyz + (size_t)b*3*NPTS;
  unsigned cnt=0;
  for (int basep=0; basep<NPTS; basep+=32){
    int pp = basep+lane;
    float dx=__fsub_rn(cx,xb[pp]);
    float dy=__fsub_rn(cy,xb[NPTS+pp]);
    float dz=__fsub_rn(cz,xb[2*NPTS+pp]);
    float d=__fadd_rn(__fadd_rn(__fmul_rn(dx,dx),__fmul_rn(dy,dy)),__fmul_rn(dz,dz));
    bool in = !(d > 0.04f);
    unsigned mm = __ballot_sync(0xffffffffu, in);
    if (in){
      unsigned r = cnt + __popc(mm & ((1u<<lane)-1u));
      if (r < NS) sidx[wl][r] = pp;
    }
    cnt += __popc(mm);
    if (cnt >= NS) break;
  }
  __syncwarp();
  unsigned c = cnt < NS ? cnt : NS;
  int first = sidx[wl][0];
  int v = (lane < (int)c) ? sidx[wl][lane] : first;
  g_ball[gw*NS + lane] = v;
}

// ---------------- points transpose (B,64,N) -> (B,N,64) --------------------
__global__ void transpose_kernel(const float* __restrict__ pts){
  __shared__ float tile[32][33];
  int b  = blockIdx.z;
  int n0 = blockIdx.x*32;
  int c0 = blockIdx.y*32;
  int tx = threadIdx.x, ty = threadIdx.y;     // 32 x 8
  const float* pb = pts + (size_t)b*DIM*NPTS;
#pragma unroll
  for (int j=0;j<32;j+=8)
    tile[ty+j][tx] = pb[(size_t)(c0+ty+j)*NPTS + n0+tx];
  __syncthreads();
  float* ob = g_ptsT + (size_t)b*NPTS*DIM;
#pragma unroll
  for (int j=0;j<32;j+=8)
    ob[(size_t)(n0+ty+j)*DIM + c0+tx] = tile[tx][ty+j];
}

// ---------------- GEMM (R5-proven core): h = act(A) @ W^T + bias -----------
// MODE 0: layer1 — gather A tile from ptsT/ball/xyz (K=68, wld=67)
// MODE 1: layer2 — A = prev H with fused BN+ReLU (K=64)
// MODE 2: layer3 — as MODE1, no H store, + max/min pool epilogue (BN=128)
template<int K, int BN, int MODE>
__global__ __launch_bounds__(256) void gemm_kernel(const float* __restrict__ A,
    const float* __restrict__ W, int wld,
    const float* __restrict__ bias, float* __restrict__ H,
    const float* __restrict__ xyz){
  constexpr bool GATHER = (MODE==0);
  constexpr bool AFF    = (MODE>=1);
  constexpr bool POOL   = (MODE==2);
  extern __shared__ float sm[];
  float* sAT   = sm;                    // [K][68]  (K-major A tile)
  float* sB    = sAT + K*68;            // [K][BN+4]
  float* sbias = sB + K*(BN+4);         // BN
  float* ssc   = sbias + BN;            // K (AFF only)
  float* ssh   = ssc + K;
  __shared__ int   sn[64];
  __shared__ float sctr[6];
  const int tid = threadIdx.x;
  const int m0  = blockIdx.x*64;

  for (int o=tid;o<BN;o+=256) sbias[o]=bias[o];
  if (AFF) for (int cc=tid; cc<K; cc+=256){ ssc[cc]=g_scale[cc]; ssh[cc]=g_shift[cc]; }
  for (int idx=tid; idx<BN*wld; idx+=256){
    int o=idx/wld, cc=idx-o*wld;
    sB[cc*(BN+4)+o]=W[idx];
  }
  if (K>wld) for (int o=tid;o<BN;o+=256) sB[(K-1)*(BN+4)+o]=0.f;

  if (GATHER){
    if (tid<64) sn[tid] = g_ball[(size_t)m0 + tid];
    if (tid>=64 && tid<70) sctr[tid-64] = g_new_xyz[(m0>>5)*3 + (tid-64)];
    __syncthreads();
    const int b = blockIdx.x >> 9;      // 512 blocks per batch
    // pts features -> rows 3..66 of sAT (K-major), same write pattern as R5
    for (int idx=tid; idx<64*16; idx+=256){
      int m=idx>>4, c4=idx&15;
      int n=sn[m];
      float4 v = *(const float4*)(g_ptsT + ((size_t)b*NPTS + n)*DIM + c4*4);
      int cc=3+c4*4;
      sAT[(cc  )*68+m]=v.x;
      sAT[(cc+1)*68+m]=v.y;
      sAT[(cc+2)*68+m]=v.z;
      sAT[(cc+3)*68+m]=v.w;
    }
    if (tid<64){
      int n=sn[tid];
      const float* xb = xyz + (size_t)b*3*NPTS;
      const int grp = (tid>>5)*3;
      sAT[0*68+tid] = __fsub_rn(xb[n],        sctr[grp+0]);
      sAT[1*68+tid] = __fsub_rn(xb[NPTS+n],   sctr[grp+1]);
      sAT[2*68+tid] = __fsub_rn(xb[2*NPTS+n], sctr[grp+2]);
      sAT[67*68+tid]= 0.f;
    }
  } else {
    __syncthreads();                    // ssc/ssh visible
    constexpr int K4 = K/4;
    const float4* A4 = (const float4*)A;
    for (int idx=tid; idx<64*K4; idx+=256){
      int m=idx/K4, c4=idx-m*K4;
      float4 v = A4[(size_t)(m0+m)*K4 + c4];
      int cc=c4*4;
      v.x = fmaxf(fmaf(v.x, ssc[cc  ], ssh[cc  ]), 0.f);
      v.y = fmaxf(fmaf(v.y, ssc[cc+1], ssh[cc+1]), 0.f);
      v.z = fmaxf(fmaf(v.z, ssc[cc+2], ssh[cc+2]), 0.f);
      v.w = fmaxf(fmaf(v.w, ssc[cc+3], ssh[cc+3]), 0.f);
      sAT[(cc  )*68+m]=v.x;
      sAT[(cc+1)*68+m]=v.y;
      sAT[(cc+2)*68+m]=v.z;
      sAT[(cc+3)*68+m]=v.w;
    }
  }
  __syncthreads();

  // ---- main loop: byte-identical to R5 ----
  constexpr int NPT = BN/16;            // 4 or 8 output cols per thread
  constexpr int NP2 = NPT/2;
  const int tm = tid>>4, tn = tid&15;
  u64 acc[4][NP2];
#pragma unroll
  for (int i=0;i<4;i++)
#pragma unroll
    for (int j=0;j<NP2;j++) acc[i][j]=pack2(sbias[tn*NPT+2*j],sbias[tn*NPT+2*j+1]);

  const float* ApT = sAT + tm*4;
  const float* Bp  = sB + tn*NPT;
#pragma unroll 4
  for (int k=0;k<K;k++){
    float4 av = *(const float4*)(ApT + k*68);
    u64 a0=pack2(av.x,av.x), a1=pack2(av.y,av.y),
        a2=pack2(av.z,av.z), a3=pack2(av.w,av.w);
    u64 b2[NP2];
    const float4* b4 = (const float4*)(Bp + k*(BN+4));
#pragma unroll
    for (int j=0;j<NP2/2;j++){
      float4 t=b4[j];
      b2[2*j]=pack2(t.x,t.y); b2[2*j+1]=pack2(t.z,t.w);
    }
#pragma unroll
    for (int j=0;j<NP2;j++){
      fma2(acc[0][j],a0,b2[j]);
      fma2(acc[1][j],a1,b2[j]);
      fma2(acc[2][j],a2,b2[j]);
      fma2(acc[3][j],a3,b2[j]);
    }
  }

  float vals[4][NPT];
#pragma unroll
  for (int i=0;i<4;i++)
#pragma unroll
    for (int j=0;j<NP2;j++) unpack2(vals[i][2*j], vals[i][2*j+1], acc[i][j]);

  if (!POOL){
#pragma unroll
    for (int i=0;i<4;i++){
      float* outp = H + (size_t)(m0+tm*4+i)*BN + tn*NPT;
#pragma unroll
      for (int j=0;j<NPT/4;j++){
        float4 t; t.x=vals[i][4*j]; t.y=vals[i][4*j+1]; t.z=vals[i][4*j+2]; t.w=vals[i][4*j+3];
        *(float4*)(outp + 4*j) = t;
      }
    }
  }

  // ---- deterministic column sum / sumsq (as R5) ----
  __syncthreads();
  float* sS  = sm;                      // [BN][16]
  float* sSS = sm + 16*BN;              // [BN][16]
#pragma unroll
  for (int j=0;j<NPT;j++){
    float v0=vals[0][j], v1=vals[1][j], v2=vals[2][j], v3=vals[3][j];
    sS [(tn*NPT+j)*16 + tm] = ((v0+v1)+v2)+v3;
    sSS[(tn*NPT+j)*16 + tm] = ((v0*v0+v1*v1)+v2*v2)+v3*v3;
  }
  __syncthreads();
  if (tid < BN){
    float s=0.f, ss=0.f;
#pragma unroll
    for (int t=0;t<16;t++){ s+=sS[tid*16+t]; ss+=sSS[tid*16+t]; }
    g_pS [(size_t)tid*NBLK + blockIdx.x] = s;
    g_pSS[(size_t)tid*NBLK + blockIdx.x] = ss;
  }

  if (POOL){
    // rows tm*4..tm*4+3 all lie in sample group tm>>3 (32 rows per sample)
    __syncthreads();
#pragma unroll
    for (int j=0;j<NPT;j++){
      float mx = fmaxf(fmaxf(vals[0][j],vals[1][j]), fmaxf(vals[2][j],vals[3][j]));
      float mn = fminf(fminf(vals[0][j],vals[1][j]), fminf(vals[2][j],vals[3][j]));
      sS [(tn*NPT+j)*16 + tm] = mx;
      sSS[(tn*NPT+j)*16 + tm] = mn;
    }
    __syncthreads();
    // 256 threads -> (grp 0..1) x (col 0..127)
    {
      int grp = tid>>7, col = tid&127;
      float mx=-3.4e38f, mn=3.4e38f;
#pragma unroll
      for (int t=0;t<8;t++){
        mx = fmaxf(mx, sS [col*16 + grp*8 + t]);
        mn = fminf(mn, sSS[col*16 + grp*8 + t]);
      }
      size_t gidx = (size_t)(blockIdx.x*2+grp)*128 + col;
      g_mx[gidx]=mx; g_mn[gidx]=mn;
    }
  }
}

// ---------------- BN stats: one block per channel ---------------------------
__global__ void bnstats_kernel(const float* __restrict__ g, const float* __restrict__ beta){
  __shared__ float sh[512];
  const int c=blockIdx.x, t=threadIdx.x;   // 256 threads
  float s=0.f, ss=0.f;
  const float* ps  = g_pS  + (size_t)c*NBLK;
  const float* pss = g_pSS + (size_t)c*NBLK;
  for (int i=t;i<NBLK;i+=256){ s+=ps[i]; ss+=pss[i]; }
  sh[t]=s; sh[256+t]=ss; __syncthreads();
  for (int o=128;o>0;o>>=1){
    if (t<o){ sh[t]+=sh[t+o]; sh[256+t]+=sh[256+t+o]; }
    __syncthreads();
  }
  if (t==0){
    const float inv = 1.0f/(float)MROWS;
    float mean = sh[0]*inv;
    float var  = sh[256]*inv - mean*mean;
    float rstd = rsqrtf(var + 1e-5f);
    float sc   = rstd*g[c];
    g_scale[c] = sc;
    g_shift[c] = beta[c] - mean*sc;
  }
}

// ---------------- final pool: norm+relu on pre-reduced max/min -------------
__global__ void pool_kernel(float* __restrict__ out){
  const int gq=blockIdx.x;                   // 0..8191 (b*1024+s)
  const int o =threadIdx.x;                  // 0..127
  const int b=gq>>10, s=gq&1023;
  const float sc=g_scale[o], sh=g_shift[o];
  const float mx=g_mx[(size_t)gq*128+o], mn=g_mn[(size_t)gq*128+o];
  float v = (sc>=0.f)? fmaf(mx,sc,sh) : fmaf(mn,sc,sh);
  out[24576 + (size_t)b*131072 + (size_t)o*1024 + s] = fmaxf(v, 0.f);
}

// ---------------- launch ----------------------------------------------------
extern "C" void kernel_launch(void* const* d_in, const int* in_sizes, int n_in,
                              void* d_out, int out_size){
  (void)in_sizes; (void)n_in; (void)out_size;
  const float* xyz = (const float*)d_in[0];
  const float* pts = (const float*)d_in[1];
  const float* w0  = (const float*)d_in[2];
  const float* b0  = (const float*)d_in[3];
  const float* gg0 = (const float*)d_in[4];
  const float* be0 = (const float*)d_in[5];
  const float* w1  = (const float*)d_in[6];
  const float* b1  = (const float*)d_in[7];
  const float* gg1 = (const float*)d_in[8];
  const float* be1 = (const float*)d_in[9];
  const float* w2  = (const float*)d_in[10];
  const float* b2  = (const float*)d_in[11];
  const float* gg2 = (const float*)d_in[12];
  const float* be2 = (const float*)d_in[13];
  float* out = (float*)d_out;

  // smem sizes (floats): K*68 + K*(BN+4) + BN + 2*K (AFF)
  const int smem1 = (68*68 + 68*68 + 64)*4;           // 37248
  const int smem2 = (64*68 + 64*68 + 64  + 2*64)*4;   // 35584
  const int smem3 = (64*68 + 64*132+ 128 + 2*64)*4;   // 52224

  cudaFuncSetAttribute(fps_kernel, cudaFuncAttributeMaxDynamicSharedMemorySize, 3*NPTS*4);
  cudaFuncSetAttribute((const void*)gemm_kernel<68,64,0>,
                       cudaFuncAttributeMaxDynamicSharedMemorySize, smem1);
  cudaFuncSetAttribute((const void*)gemm_kernel<64,64,1>,
                       cudaFuncAttributeMaxDynamicSharedMemorySize, smem2);
  cudaFuncSetAttribute((const void*)gemm_kernel<64,128,2>,
                       cudaFuncAttributeMaxDynamicSharedMemorySize, smem3);

  float *pH1,*pH2;
  cudaGetSymbolAddress((void**)&pH1, g_h1);
  cudaGetSymbolAddress((void**)&pH2, g_h2);

  fps_kernel<<<BATCH, 1024, 3*NPTS*4>>>(xyz);
  newxyz_kernel<<<BATCH, SPTS>>>(xyz, out);
  ball_kernel<<<1024, 256>>>(xyz);
  transpose_kernel<<<dim3(NPTS/32, DIM/32, BATCH), dim3(32,8)>>>(pts);

  gemm_kernel<68,64,0><<<NBLK, 256, smem1>>>(nullptr, w0, 67, b0, pH1, xyz);
  bnstats_kernel<<<64, 256>>>(gg0, be0);

  gemm_kernel<64,64,1><<<NBLK, 256, smem2>>>(pH1, w1, 64, b1, pH2, xyz);
  bnstats_kernel<<<64, 256>>>(gg1, be1);

  gemm_kernel<64,128,2><<<NBLK, 256, smem3>>>(pH2, w2, 64, b2, nullptr, xyz);
  bnstats_kernel<<<128, 256>>>(gg2, be2);

  pool_kernel<<<BATCH*SPTS, 128>>>(out);
}

// round 9
// speedup vs baseline: 1.8921x; 1.3387x over previous
#include <cuda_runtime.h>
#include <cstdint>

#define BATCH   8
#define NPTS    8192
#define DIM     64
#define SPTS    1024      // NPOINT
#define NS      32        // NSAMPLE
#define MROWS   (BATCH*SPTS*NS)   // 262144
#define NBLK    (MROWS/64)        // 4096 gemm blocks

typedef unsigned long long u64;

// ---------------- f32x2 packed helpers --------------------------------------
__device__ __forceinline__ u64 pack2(float lo, float hi){
  u64 r; asm("mov.b64 %0,{%1,%2};" : "=l"(r) : "f"(lo), "f"(hi)); return r;
}
__device__ __forceinline__ void unpack2(float& lo, float& hi, u64 p){
  asm("mov.b64 {%0,%1},%2;" : "=f"(lo), "=f"(hi) : "l"(p));
}
__device__ __forceinline__ u64 add2(u64 a, u64 b){
  u64 r; asm("add.rn.f32x2 %0,%1,%2;" : "=l"(r) : "l"(a), "l"(b)); return r;
}
__device__ __forceinline__ u64 mul2(u64 a, u64 b){
  u64 r; asm("mul.rn.f32x2 %0,%1,%2;" : "=l"(r) : "l"(a), "l"(b)); return r;
}
__device__ __forceinline__ void fma2(u64& d, u64 a, u64 b){
  asm("fma.rn.f32x2 %0,%1,%2,%0;" : "+l"(d) : "l"(a), "l"(b));
}

// ---------------- scratch ---------------------------------------------------
__device__ int   g_fps_idx[BATCH*SPTS];
__device__ float g_new_xyz[BATCH*SPTS*3];
__device__ int   g_ball[BATCH*SPTS*NS];
__device__ float g_ptsT[BATCH*NPTS*DIM];
__device__ float g_h1[(size_t)MROWS*64];
__device__ float g_h2[(size_t)MROWS*64];
__device__ float g_mx[(size_t)BATCH*SPTS*128];
__device__ float g_mn[(size_t)BATCH*SPTS*128];
__device__ float g_pS [(size_t)128*NBLK];   // channel-major
__device__ float g_pSS[(size_t)128*NBLK];
__device__ float g_scale[128];
__device__ float g_shift[128];

// ---------------- FPS: REDUX-based value phase + guarded index phase --------
__global__ __launch_bounds__(1024,1) void fps_kernel(const float* __restrict__ xyz){
  extern __shared__ float sxyz[];            // 3*8192 floats
  __shared__ unsigned swarp[32];
  __shared__ unsigned svbits;
  __shared__ unsigned srev[2];
  const int b   = blockIdx.x;
  const int tid = threadIdx.x;
  const float* xb = xyz + (size_t)b*3*NPTS;
  for (int i=tid; i<3*NPTS; i+=1024) sxyz[i]=xb[i];
  if (tid<2) srev[tid]=0u;
  __syncthreads();

  u64 rx2[4], ry2[4], rz2[4];
  float rdl[4], rdh[4];
#pragma unroll
  for (int j=0;j<4;j++){
    int plo=j*1024+tid, phi=(j+4)*1024+tid;
    rx2[j]=pack2(sxyz[plo],       sxyz[phi]);
    ry2[j]=pack2(sxyz[NPTS+plo],  sxyz[NPTS+phi]);
    rz2[j]=pack2(sxyz[2*NPTS+plo],sxyz[2*NPTS+phi]);
    rdl[j]=1e10f; rdh[j]=1e10f;
  }
  int far=0, p=0;
  const int lane=tid&31, wid=tid>>5;
  const unsigned base = (unsigned)(NPTS-1-tid);

  for (int it=0; it<SPTS; ++it){
    if (tid==0) g_fps_idx[b*SPTS+it]=far;
    const float cx=sxyz[far], cy=sxyz[NPTS+far], cz=sxyz[2*NPTS+far];
    const u64 ncx=pack2(-cx,-cx), ncy=pack2(-cy,-cy), ncz=pack2(-cz,-cz);
    float m=0.f;
#pragma unroll
    for (int j=0;j<4;j++){
      u64 dx=add2(rx2[j],ncx);            // x + (-c) == x - c (IEEE)
      u64 dy=add2(ry2[j],ncy);
      u64 dz=add2(rz2[j],ncz);
      // exact ((dx^2+dy^2)+dz^2): separate mul + add roundings per lane
      u64 s2=add2(add2(mul2(dx,dx),mul2(dy,dy)),mul2(dz,dz));
      float dl,dh; unpack2(dl,dh,s2);
      float nl=fminf(rdl[j],dl), nh=fminf(rdh[j],dh);
      rdl[j]=nl; rdh[j]=nh;
      m = fmaxf(m, fmaxf(nl,nh));
    }
    // distances >= 0: float order == u32 bit order. One REDUX per warp.
    const unsigned wbits = __reduce_max_sync(0xffffffffu, __float_as_uint(m));
    if (lane==0) swarp[wid]=wbits;
    __syncthreads();                       // (1) warp maxima ready
    if (wid==0){
      unsigned v = __reduce_max_sync(0xffffffffu, swarp[lane]);
      if (lane==0) svbits=v;
    }
    __syncthreads();                       // (2) block max ready
    const float vmax = __uint_as_float(svbits);
    if (wbits==svbits){                    // WARP-UNIFORM guard (wbits = warp max)
      unsigned rev=0u;
#pragma unroll
      for (int j=0;j<4;j++){
        if (rdl[j]==vmax){ unsigned r=base-(unsigned)(j<<10);     rev = r>rev?r:rev; }
        if (rdh[j]==vmax){ unsigned r=base-(unsigned)((j+4)<<10); rev = r>rev?r:rev; }
      }
      rev = __reduce_max_sync(0xffffffffu, rev);
      if (lane==0) atomicMax(&srev[p], rev);
    }
    __syncthreads();                       // (3) index ready
    far = (NPTS-1) - (int)srev[p];         // srev==0 => point 8191 (consistent)
    if (tid==0) srev[p^1]=0u;
    p ^= 1;
  }
}

// ---------------- new_xyz gather + first output section --------------------
__global__ void newxyz_kernel(const float* __restrict__ xyz, float* __restrict__ out){
  int b=blockIdx.x, s=threadIdx.x;
  int idx = g_fps_idx[b*SPTS+s];
#pragma unroll
  for (int d=0; d<3; d++){
    float v = xyz[(size_t)b*3*NPTS + (size_t)d*NPTS + idx];
    g_new_xyz[(b*SPTS+s)*3+d]=v;
    out[(size_t)b*3*SPTS + (size_t)d*SPTS + s]=v;
  }
}

// ---------------- ball query: one warp per query ---------------------------
__global__ void ball_kernel(const float* __restrict__ xyz){
  const int gw   = (blockIdx.x*blockDim.x + threadIdx.x) >> 5;  // 0..8191
  const int lane = threadIdx.x & 31;
  const int wl   = threadIdx.x >> 5;
  const int b = gw >> 10;
  __shared__ int sidx[8][NS];
  const float cx=g_new_xyz[gw*3+0], cy=g_new_xyz[gw*3+1], cz=g_new_xyz[gw*3+2];
  const float* xb = xyz + (size_t)b*3*NPTS;
  unsigned cnt=0;
  for (int basep=0; basep<NPTS; basep+=32){
    int pp = basep+lane;
    float dx=__fsub_rn(cx,xb[pp]);
    float dy=__fsub_rn(cy,xb[NPTS+pp]);
    float dz=__fsub_rn(cz,xb[2*NPTS+pp]);
    float d=__fadd_rn(__fadd_rn(__fmul_rn(dx,dx),__fmul_rn(dy,dy)),__fmul_rn(dz,dz));
    bool in = !(d > 0.04f);
    unsigned mm = __ballot_sync(0xffffffffu, in);
    if (in){
      unsigned r = cnt + __popc(mm & ((1u<<lane)-1u));
      if (r < NS) sidx[wl][r] = pp;
    }
    cnt += __popc(mm);
    if (cnt >= NS) break;
  }
  __syncwarp();
  unsigned c = cnt < NS ? cnt : NS;
  int first = sidx[wl][0];
  int v = (lane < (int)c) ? sidx[wl][lane] : first;
  g_ball[gw*NS + lane] = v;
}

// ---------------- points transpose (B,64,N) -> (B,N,64) --------------------
__global__ void transpose_kernel(const float* __restrict__ pts){
  __shared__ float tile[32][33];
  int b  = blockIdx.z;
  int n0 = blockIdx.x*32;
  int c0 = blockIdx.y*32;
  int tx = threadIdx.x, ty = threadIdx.y;     // 32 x 8
  const float* pb = pts + (size_t)b*DIM*NPTS;
#pragma unroll
  for (int j=0;j<32;j+=8)
    tile[ty+j][tx] = pb[(size_t)(c0+ty+j)*NPTS + n0+tx];
  __syncthreads();
  float* ob = g_ptsT + (size_t)b*NPTS*DIM;
#pragma unroll
  for (int j=0;j<32;j+=8)
    ob[(size_t)(n0+ty+j)*DIM + c0+tx] = tile[tx][ty+j];
}

// ---------------- GEMM (R5-proven core): h = act(A) @ W^T + bias -----------
// MODE 0: layer1 — gather A tile from ptsT/ball/xyz (K=68, wld=67)
// MODE 1: layer2 — A = prev H with fused BN+ReLU (K=64)
// MODE 2: layer3 — as MODE1, no H store, + max/min pool epilogue (BN=128)
template<int K, int BN, int MODE>
__global__ __launch_bounds__(256) void gemm_kernel(const float* __restrict__ A,
    const float* __restrict__ W, int wld,
    const float* __restrict__ bias, float* __restrict__ H,
    const float* __restrict__ xyz){
  constexpr bool GATHER = (MODE==0);
  constexpr bool AFF    = (MODE>=1);
  constexpr bool POOL   = (MODE==2);
  extern __shared__ float sm[];
  float* sAT   = sm;                    // [K][68]  (K-major A tile)
  float* sB    = sAT + K*68;            // [K][BN+4]
  float* sbias = sB + K*(BN+4);         // BN
  float* ssc   = sbias + BN;            // K (AFF only)
  float* ssh   = ssc + K;
  __shared__ int   sn[64];
  __shared__ float sctr[6];
  const int tid = threadIdx.x;
  const int m0  = blockIdx.x*64;

  for (int o=tid;o<BN;o+=256) sbias[o]=bias[o];
  if (AFF) for (int cc=tid; cc<K; cc+=256){ ssc[cc]=g_scale[cc]; ssh[cc]=g_shift[cc]; }
  for (int idx=tid; idx<BN*wld; idx+=256){
    int o=idx/wld, cc=idx-o*wld;
    sB[cc*(BN+4)+o]=W[idx];
  }
  if (K>wld) for (int o=tid;o<BN;o+=256) sB[(K-1)*(BN+4)+o]=0.f;

  if (GATHER){
    if (tid<64) sn[tid] = g_ball[(size_t)m0 + tid];
    if (tid>=64 && tid<70) sctr[tid-64] = g_new_xyz[(m0>>5)*3 + (tid-64)];
    __syncthreads();
    const int b = blockIdx.x >> 9;      // 512 blocks per batch
    // m-fast ordering: warp spans m 0..31 -> conflict-free STS banks
    for (int idx=tid; idx<64*16; idx+=256){
      int c4 = idx >> 6;                // 0..15
      int m  = idx & 63;                // 0..63
      int n  = sn[m];
      float4 v = *(const float4*)(g_ptsT + ((size_t)b*NPTS + n)*DIM + c4*4);
      int cc=3+c4*4;
      sAT[(cc  )*68+m]=v.x;
      sAT[(cc+1)*68+m]=v.y;
      sAT[(cc+2)*68+m]=v.z;
      sAT[(cc+3)*68+m]=v.w;
    }
    if (tid<64){
      int n=sn[tid];
      const float* xb = xyz + (size_t)b*3*NPTS;
      const int grp = (tid>>5)*3;
      sAT[0*68+tid] = __fsub_rn(xb[n],        sctr[grp+0]);
      sAT[1*68+tid] = __fsub_rn(xb[NPTS+n],   sctr[grp+1]);
      sAT[2*68+tid] = __fsub_rn(xb[2*NPTS+n], sctr[grp+2]);
      sAT[67*68+tid]= 0.f;
    }
  } else {
    __syncthreads();                    // ssc/ssh visible
    constexpr int K4 = K/4;
    const float4* A4 = (const float4*)A;
    for (int idx=tid; idx<64*K4; idx+=256){
      int m=idx/K4, c4=idx-m*K4;
      float4 v = A4[(size_t)(m0+m)*K4 + c4];
      int cc=c4*4;
      v.x = fmaxf(fmaf(v.x, ssc[cc  ], ssh[cc  ]), 0.f);
      v.y = fmaxf(fmaf(v.y, ssc[cc+1], ssh[cc+1]), 0.f);
      v.z = fmaxf(fmaf(v.z, ssc[cc+2], ssh[cc+2]), 0.f);
      v.w = fmaxf(fmaf(v.w, ssc[cc+3], ssh[cc+3]), 0.f);
      sAT[(cc  )*68+m]=v.x;
      sAT[(cc+1)*68+m]=v.y;
      sAT[(cc+2)*68+m]=v.z;
      sAT[(cc+3)*68+m]=v.w;
    }
  }
  __syncthreads();

  // ---- main loop: byte-identical to R5/R7 ----
  constexpr int NPT = BN/16;            // 4 or 8 output cols per thread
  constexpr int NP2 = NPT/2;
  const int tm = tid>>4, tn = tid&15;
  u64 acc[4][NP2];
#pragma unroll
  for (int i=0;i<4;i++)
#pragma unroll
    for (int j=0;j<NP2;j++) acc[i][j]=pack2(sbias[tn*NPT+2*j],sbias[tn*NPT+2*j+1]);

  const float* ApT = sAT + tm*4;
  const float* Bp  = sB + tn*NPT;
#pragma unroll 4
  for (int k=0;k<K;k++){
    float4 av = *(const float4*)(ApT + k*68);
    u64 a0=pack2(av.x,av.x), a1=pack2(av.y,av.y),
        a2=pack2(av.z,av.z), a3=pack2(av.w,av.w);
    u64 b2[NP2];
    const float4* b4 = (const float4*)(Bp + k*(BN+4));
#pragma unroll
    for (int j=0;j<NP2/2;j++){
      float4 t=b4[j];
      b2[2*j]=pack2(t.x,t.y); b2[2*j+1]=pack2(t.z,t.w);
    }
#pragma unroll
    for (int j=0;j<NP2;j++){
      fma2(acc[0][j],a0,b2[j]);
      fma2(acc[1][j],a1,b2[j]);
      fma2(acc[2][j],a2,b2[j]);
      fma2(acc[3][j],a3,b2[j]);
    }
  }

  float vals[4][NPT];
#pragma unroll
  for (int i=0;i<4;i++)
#pragma unroll
    for (int j=0;j<NP2;j++) unpack2(vals[i][2*j], vals[i][2*j+1], acc[i][j]);

  if (!POOL){
#pragma unroll
    for (int i=0;i<4;i++){
      float* outp = H + (size_t)(m0+tm*4+i)*BN + tn*NPT;
#pragma unroll
      for (int j=0;j<NPT/4;j++){
        float4 t; t.x=vals[i][4*j]; t.y=vals[i][4*j+1]; t.z=vals[i][4*j+2]; t.w=vals[i][4*j+3];
        *(float4*)(outp + 4*j) = t;
      }
    }
  }

  // ---- deterministic column sum / sumsq (as R5) ----
  __syncthreads();
  float* sS  = sm;                      // [BN][16]
  float* sSS = sm + 16*BN;              // [BN][16]
#pragma unroll
  for (int j=0;j<NPT;j++){
    float v0=vals[0][j], v1=vals[1][j], v2=vals[2][j], v3=vals[3][j];
    sS [(tn*NPT+j)*16 + tm] = ((v0+v1)+v2)+v3;
    sSS[(tn*NPT+j)*16 + tm] = ((v0*v0+v1*v1)+v2*v2)+v3*v3;
  }
  __syncthreads();
  if (tid < BN){
    float s=0.f, ss=0.f;
#pragma unroll
    for (int t=0;t<16;t++){ s+=sS[tid*16+t]; ss+=sSS[tid*16+t]; }
    g_pS [(size_t)tid*NBLK + blockIdx.x] = s;
    g_pSS[(size_t)tid*NBLK + blockIdx.x] = ss;
  }

  if (POOL){
    // rows tm*4..tm*4+3 all lie in sample group tm>>3 (32 rows per sample)
    __syncthreads();
#pragma unroll
    for (int j=0;j<NPT;j++){
      float mx = fmaxf(fmaxf(vals[0][j],vals[1][j]), fmaxf(vals[2][j],vals[3][j]));
      float mn = fminf(fminf(vals[0][j],vals[1][j]), fminf(vals[2][j],vals[3][j]));
      sS [(tn*NPT+j)*16 + tm] = mx;
      sSS[(tn*NPT+j)*16 + tm] = mn;
    }
    __syncthreads();
    // 256 threads -> (grp 0..1) x (col 0..127)
    {
      int grp = tid>>7, col = tid&127;
      float mx=-3.4e38f, mn=3.4e38f;
#pragma unroll
      for (int t=0;t<8;t++){
        mx = fmaxf(mx, sS [col*16 + grp*8 + t]);
        mn = fminf(mn, sSS[col*16 + grp*8 + t]);
      }
      size_t gidx = (size_t)(blockIdx.x*2+grp)*128 + col;
      g_mx[gidx]=mx; g_mn[gidx]=mn;
    }
  }
}

// ---------------- BN stats: one block per channel ---------------------------
__global__ void bnstats_kernel(const float* __restrict__ g, const float* __restrict__ beta){
  __shared__ float sh[512];
  const int c=blockIdx.x, t=threadIdx.x;   // 256 threads
  float s=0.f, ss=0.f;
  const float* ps  = g_pS  + (size_t)c*NBLK;
  const float* pss = g_pSS + (size_t)c*NBLK;
  for (int i=t;i<NBLK;i+=256){ s+=ps[i]; ss+=pss[i]; }
  sh[t]=s; sh[256+t]=ss; __syncthreads();
  for (int o=128;o>0;o>>=1){
    if (t<o){ sh[t]+=sh[t+o]; sh[256+t]+=sh[256+t+o]; }
    __syncthreads();
  }
  if (t==0){
    const float inv = 1.0f/(float)MROWS;
    float mean = sh[0]*inv;
    float var  = sh[256]*inv - mean*mean;
    float rstd = rsqrtf(var + 1e-5f);
    float sc   = rstd*g[c];
    g_scale[c] = sc;
    g_shift[c] = beta[c] - mean*sc;
  }
}

// ---------------- final pool: norm+relu on pre-reduced max/min -------------
__global__ void pool_kernel(float* __restrict__ out){
  const int gq=blockIdx.x;                   // 0..8191 (b*1024+s)
  const int o =threadIdx.x;                  // 0..127
  const int b=gq>>10, s=gq&1023;
  const float sc=g_scale[o], sh=g_shift[o];
  const float mx=g_mx[(size_t)gq*128+o], mn=g_mn[(size_t)gq*128+o];
  float v = (sc>=0.f)? fmaf(mx,sc,sh) : fmaf(mn,sc,sh);
  out[24576 + (size_t)b*131072 + (size_t)o*1024 + s] = fmaxf(v, 0.f);
}

// ---------------- launch ----------------------------------------------------
extern "C" void kernel_launch(void* const* d_in, const int* in_sizes, int n_in,
                              void* d_out, int out_size){
  (void)in_sizes; (void)n_in; (void)out_size;
  const float* xyz = (const float*)d_in[0];
  const float* pts = (const float*)d_in[1];
  const float* w0  = (const float*)d_in[2];
  const float* b0  = (const float*)d_in[3];
  const float* gg0 = (const float*)d_in[4];
  const float* be0 = (const float*)d_in[5];
  const float* w1  = (const float*)d_in[6];
  const float* b1  = (const float*)d_in[7];
  const float* gg1 = (const float*)d_in[8];
  const float* be1 = (const float*)d_in[9];
  const float* w2  = (const float*)d_in[10];
  const float* b2  = (const float*)d_in[11];
  const float* gg2 = (const float*)d_in[12];
  const float* be2 = (const float*)d_in[13];
  float* out = (float*)d_out;

  // smem sizes (floats): K*68 + K*(BN+4) + BN + 2*K (AFF)
  const int smem1 = (68*68 + 68*68 + 64)*4;           // 37248
  const int smem2 = (64*68 + 64*68 + 64  + 2*64)*4;   // 35584
  const int smem3 = (64*68 + 64*132+ 128 + 2*64)*4;   // 52224

  cudaFuncSetAttribute(fps_kernel, cudaFuncAttributeMaxDynamicSharedMemorySize, 3*NPTS*4);
  cudaFuncSetAttribute((const void*)gemm_kernel<68,64,0>,
                       cudaFuncAttributeMaxDynamicSharedMemorySize, smem1);
  cudaFuncSetAttribute((const void*)gemm_kernel<64,64,1>,
                       cudaFuncAttributeMaxDynamicSharedMemorySize, smem2);
  cudaFuncSetAttribute((const void*)gemm_kernel<64,128,2>,
                       cudaFuncAttributeMaxDynamicSharedMemorySize, smem3);

  float *pH1,*pH2;
  cudaGetSymbolAddress((void**)&pH1, g_h1);
  cudaGetSymbolAddress((void**)&pH2, g_h2);

  fps_kernel<<<BATCH, 1024, 3*NPTS*4>>>(xyz);
  newxyz_kernel<<<BATCH, SPTS>>>(xyz, out);
  ball_kernel<<<1024, 256>>>(xyz);
  transpose_kernel<<<dim3(NPTS/32, DIM/32, BATCH), dim3(32,8)>>>(pts);

  gemm_kernel<68,64,0><<<NBLK, 256, smem1>>>(nullptr, w0, 67, b0, pH1, xyz);
  bnstats_kernel<<<64, 256>>>(gg0, be0);

  gemm_kernel<64,64,1><<<NBLK, 256, smem2>>>(pH1, w1, 64, b1, pH2, xyz);
  bnstats_kernel<<<64, 256>>>(gg1, be1);

  gemm_kernel<64,128,2><<<NBLK, 256, smem3>>>(pH2, w2, 64, b2, nullptr, xyz);
  bnstats_kernel<<<128, 256>>>(gg2, be2);

  pool_kernel<<<BATCH*SPTS, 128>>>(out);
}

// round 11
// speedup vs baseline: 1.9404x; 1.0255x over previous
#include <cuda_runtime.h>
#include <cstdint>

#define BATCH   8
#define NPTS    8192
#define DIM     64
#define SPTS    1024      // NPOINT
#define NS      32        // NSAMPLE
#define MROWS   (BATCH*SPTS*NS)   // 262144
#define NBLK    (MROWS/64)        // 4096 gemm blocks

typedef unsigned long long u64;

// ---------------- f32x2 packed helpers --------------------------------------
__device__ __forceinline__ u64 pack2(float lo, float hi){
  u64 r; asm("mov.b64 %0,{%1,%2};" : "=l"(r) : "f"(lo), "f"(hi)); return r;
}
__device__ __forceinline__ void unpack2(float& lo, float& hi, u64 p){
  asm("mov.b64 {%0,%1},%2;" : "=f"(lo), "=f"(hi) : "l"(p));
}
__device__ __forceinline__ u64 add2(u64 a, u64 b){
  u64 r; asm("add.rn.f32x2 %0,%1,%2;" : "=l"(r) : "l"(a), "l"(b)); return r;
}
__device__ __forceinline__ u64 mul2(u64 a, u64 b){
  u64 r; asm("mul.rn.f32x2 %0,%1,%2;" : "=l"(r) : "l"(a), "l"(b)); return r;
}
__device__ __forceinline__ void fma2(u64& d, u64 a, u64 b){
  asm("fma.rn.f32x2 %0,%1,%2,%0;" : "+l"(d) : "l"(a), "l"(b));
}

// ---------------- scratch ---------------------------------------------------
__device__ int   g_fps_idx[BATCH*SPTS];
__device__ float g_new_xyz[BATCH*SPTS*3];
__device__ int   g_ball[BATCH*SPTS*NS];
__device__ float g_ptsT[BATCH*NPTS*DIM];
__device__ float g_h1[(size_t)MROWS*64];
__device__ float g_h2[(size_t)MROWS*64];
__device__ float g_mx[(size_t)BATCH*SPTS*128];
__device__ float g_mn[(size_t)BATCH*SPTS*128];
__device__ float g_pS [(size_t)128*NBLK];   // channel-major
__device__ float g_pSS[(size_t)128*NBLK];
__device__ float g_scale[128];
__device__ float g_shift[128];

// ---------------- FPS: REDUX value phase, single-stage block reduction ------
__global__ __launch_bounds__(1024,1) void fps_kernel(const float* __restrict__ xyz){
  extern __shared__ float sxyz[];            // 3*8192 floats
  __shared__ unsigned swarp[32];
  __shared__ unsigned srev[2];
  const int b   = blockIdx.x;
  const int tid = threadIdx.x;
  const float* xb = xyz + (size_t)b*3*NPTS;
  for (int i=tid; i<3*NPTS; i+=1024) sxyz[i]=xb[i];
  if (tid<2) srev[tid]=0u;
  __syncthreads();

  // pair j: lane-lo = point j*1024+tid, lane-hi = point (j+4)*1024+tid
  u64 rx2[4], ry2[4], rz2[4];
  float rdl[4], rdh[4];
#pragma unroll
  for (int j=0;j<4;j++){
    int plo=j*1024+tid, phi=(j+4)*1024+tid;
    rx2[j]=pack2(sxyz[plo],       sxyz[phi]);
    ry2[j]=pack2(sxyz[NPTS+plo],  sxyz[NPTS+phi]);
    rz2[j]=pack2(sxyz[2*NPTS+plo],sxyz[2*NPTS+phi]);
    rdl[j]=1e10f; rdh[j]=1e10f;
  }
  int far=0, p=0;
  const int lane=tid&31, wid=tid>>5;
  const unsigned base = (unsigned)(NPTS-1-tid);

  for (int it=0; it<SPTS; ++it){
    if (tid==0) g_fps_idx[b*SPTS+it]=far;
    const float cx=sxyz[far], cy=sxyz[NPTS+far], cz=sxyz[2*NPTS+far];
    const u64 ncx=pack2(-cx,-cx), ncy=pack2(-cy,-cy), ncz=pack2(-cz,-cz);
    float m=0.f;
#pragma unroll
    for (int j=0;j<4;j++){
      u64 dx=add2(rx2[j],ncx);            // x + (-c) == x - c (IEEE)
      u64 dy=add2(ry2[j],ncy);
      u64 dz=add2(rz2[j],ncz);
      // exact ((dx^2+dy^2)+dz^2): separate mul + add roundings per lane
      u64 s2=add2(add2(mul2(dx,dx),mul2(dy,dy)),mul2(dz,dz));
      float dl,dh; unpack2(dl,dh,s2);
      float nl=fminf(rdl[j],dl), nh=fminf(rdh[j],dh);
      rdl[j]=nl; rdh[j]=nh;
      m = fmaxf(m, fmaxf(nl,nh));
    }
    // distances >= 0: float order == u32 bit order. One REDUX per warp.
    const unsigned wbits = __reduce_max_sync(0xffffffffu, __float_as_uint(m));
    if (lane==0) swarp[wid]=wbits;
    __syncthreads();                       // (1) warp maxima ready
    // every warp reduces the 32 warp-maxima itself (conflict-free LDS read)
    const unsigned vbits = __reduce_max_sync(0xffffffffu, swarp[lane]);
    const float vmax = __uint_as_float(vbits);
    if (wbits==vbits){                     // WARP-UNIFORM guard
      unsigned rev=0u;
#pragma unroll
      for (int j=0;j<4;j++){
        if (rdl[j]==vmax){ unsigned r=base-(unsigned)(j<<10);     rev = r>rev?r:rev; }
        if (rdh[j]==vmax){ unsigned r=base-(unsigned)((j+4)<<10); rev = r>rev?r:rev; }
      }
      rev = __reduce_max_sync(0xffffffffu, rev);
      if (lane==0) atomicMax(&srev[p], rev);
    }
    __syncthreads();                       // (2) index ready
    far = (NPTS-1) - (int)srev[p];         // srev==0 => point 8191 (consistent)
    if (tid==0) srev[p^1]=0u;
    p ^= 1;
  }
}

// ---------------- new_xyz gather + first output section --------------------
__global__ void newxyz_kernel(const float* __restrict__ xyz, float* __restrict__ out){
  int b=blockIdx.x, s=threadIdx.x;
  int idx = g_fps_idx[b*SPTS+s];
#pragma unroll
  for (int d=0; d<3; d++){
    float v = xyz[(size_t)b*3*NPTS + (size_t)d*NPTS + idx];
    g_new_xyz[(b*SPTS+s)*3+d]=v;
    out[(size_t)b*3*SPTS + (size_t)d*SPTS + s]=v;
  }
}

// ---------------- ball query: one warp per query ---------------------------
__global__ void ball_kernel(const float* __restrict__ xyz){
  const int gw   = (blockIdx.x*blockDim.x + threadIdx.x) >> 5;  // 0..8191
  const int lane = threadIdx.x & 31;
  const int wl   = threadIdx.x >> 5;
  const int b = gw >> 10;
  __shared__ int sidx[8][NS];
  const float cx=g_new_xyz[gw*3+0], cy=g_new_xyz[gw*3+1], cz=g_new_xyz[gw*3+2];
  const float* xb = xyz + (size_t)b*3*NPTS;
  unsigned cnt=0;
  for (int basep=0; basep<NPTS; basep+=32){
    int pp = basep+lane;
    float dx=__fsub_rn(cx,xb[pp]);
    float dy=__fsub_rn(cy,xb[NPTS+pp]);
    float dz=__fsub_rn(cz,xb[2*NPTS+pp]);
    float d=__fadd_rn(__fadd_rn(__fmul_rn(dx,dx),__fmul_rn(dy,dy)),__fmul_rn(dz,dz));
    bool in = !(d > 0.04f);
    unsigned mm = __ballot_sync(0xffffffffu, in);
    if (in){
      unsigned r = cnt + __popc(mm & ((1u<<lane)-1u));
      if (r < NS) sidx[wl][r] = pp;
    }
    cnt += __popc(mm);
    if (cnt >= NS) break;
  }
  __syncwarp();
  unsigned c = cnt < NS ? cnt : NS;
  int first = sidx[wl][0];
  int v = (lane < (int)c) ? sidx[wl][lane] : first;
  g_ball[gw*NS + lane] = v;
}

// ---------------- points transpose (B,64,N) -> (B,N,64) --------------------
__global__ void transpose_kernel(const float* __restrict__ pts){
  __shared__ float tile[32][33];
  int b  = blockIdx.z;
  int n0 = blockIdx.x*32;
  int c0 = blockIdx.y*32;
  int tx = threadIdx.x, ty = threadIdx.y;     // 32 x 8
  const float* pb = pts + (size_t)b*DIM*NPTS;
#pragma unroll
  for (int j=0;j<32;j+=8)
    tile[ty+j][tx] = pb[(size_t)(c0+ty+j)*NPTS + n0+tx];
  __syncthreads();
  float* ob = g_ptsT + (size_t)b*NPTS*DIM;
#pragma unroll
  for (int j=0;j<32;j+=8)
    ob[(size_t)(n0+ty+j)*DIM + c0+tx] = tile[tx][ty+j];
}

// ---------------- GEMM (R5-proven core): h = act(A) @ W^T + bias -----------
// MODE 0: layer1 — gather A tile from ptsT/ball/xyz (K=68, wld=67)
// MODE 1: layer2 — A = prev H with fused BN+ReLU (K=64)
// MODE 2: layer3 — as MODE1, no H store, + max/min pool epilogue (BN=128)
template<int K, int BN, int MODE>
__global__ __launch_bounds__(256) void gemm_kernel(const float* __restrict__ A,
    const float* __restrict__ W, int wld,
    const float* __restrict__ bias, float* __restrict__ H,
    const float* __restrict__ xyz){
  constexpr bool GATHER = (MODE==0);
  constexpr bool AFF    = (MODE>=1);
  constexpr bool POOL   = (MODE==2);
  extern __shared__ float sm[];
  float* sAT   = sm;                    // [K][68]  (K-major A tile)
  float* sB    = sAT + K*68;            // [K][BN+4]
  float* sbias = sB + K*(BN+4);         // BN
  float* ssc   = sbias + BN;            // K (AFF only)
  float* ssh   = ssc + K;
  __shared__ int   sn[64];
  __shared__ float sctr[6];
  const int tid = threadIdx.x;
  const int m0  = blockIdx.x*64;

  for (int o=tid;o<BN;o+=256) sbias[o]=bias[o];
  if (AFF) for (int cc=tid; cc<K; cc+=256){ ssc[cc]=g_scale[cc]; ssh[cc]=g_shift[cc]; }
  for (int idx=tid; idx<BN*wld; idx+=256){
    int o=idx/wld, cc=idx-o*wld;
    sB[cc*(BN+4)+o]=W[idx];
  }
  if (K>wld) for (int o=tid;o<BN;o+=256) sB[(K-1)*(BN+4)+o]=0.f;

  if (GATHER){
    if (tid<64) sn[tid] = g_ball[(size_t)m0 + tid];
    if (tid>=64 && tid<70) sctr[tid-64] = g_new_xyz[(m0>>5)*3 + (tid-64)];
    __syncthreads();
    const int b = blockIdx.x >> 9;      // 512 blocks per batch
    // m-fast ordering: warp spans m 0..31 -> conflict-free STS banks
    for (int idx=tid; idx<64*16; idx+=256){
      int c4 = idx >> 6;                // 0..15
      int m  = idx & 63;                // 0..63
      int n  = sn[m];
      float4 v = *(const float4*)(g_ptsT + ((size_t)b*NPTS + n)*DIM + c4*4);
      int cc=3+c4*4;
      sAT[(cc  )*68+m]=v.x;
      sAT[(cc+1)*68+m]=v.y;
      sAT[(cc+2)*68+m]=v.z;
      sAT[(cc+3)*68+m]=v.w;
    }
    if (tid<64){
      int n=sn[tid];
      const float* xb = xyz + (size_t)b*3*NPTS;
      const int grp = (tid>>5)*3;
      sAT[0*68+tid] = __fsub_rn(xb[n],        sctr[grp+0]);
      sAT[1*68+tid] = __fsub_rn(xb[NPTS+n],   sctr[grp+1]);
      sAT[2*68+tid] = __fsub_rn(xb[2*NPTS+n], sctr[grp+2]);
      sAT[67*68+tid]= 0.f;
    }
  } else {
    __syncthreads();                    // ssc/ssh visible
    constexpr int K4 = K/4;
    const float4* A4 = (const float4*)A;
    for (int idx=tid; idx<64*K4; idx+=256){
      int m=idx/K4, c4=idx-m*K4;
      float4 v = A4[(size_t)(m0+m)*K4 + c4];
      int cc=c4*4;
      v.x = fmaxf(fmaf(v.x, ssc[cc  ], ssh[cc  ]), 0.f);
      v.y = fmaxf(fmaf(v.y, ssc[cc+1], ssh[cc+1]), 0.f);
      v.z = fmaxf(fmaf(v.z, ssc[cc+2], ssh[cc+2]), 0.f);
      v.w = fmaxf(fmaf(v.w, ssc[cc+3], ssh[cc+3]), 0.f);
      sAT[(cc  )*68+m]=v.x;
      sAT[(cc+1)*68+m]=v.y;
      sAT[(cc+2)*68+m]=v.z;
      sAT[(cc+3)*68+m]=v.w;
    }
  }
  __syncthreads();

  // ---- main loop: byte-identical to R5/R7/R9 ----
  constexpr int NPT = BN/16;            // 4 or 8 output cols per thread
  constexpr int NP2 = NPT/2;
  const int tm = tid>>4, tn = tid&15;
  u64 acc[4][NP2];
#pragma unroll
  for (int i=0;i<4;i++)
#pragma unroll
    for (int j=0;j<NP2;j++) acc[i][j]=pack2(sbias[tn*NPT+2*j],sbias[tn*NPT+2*j+1]);

  const float* ApT = sAT + tm*4;
  const float* Bp  = sB + tn*NPT;
#pragma unroll 4
  for (int k=0;k<K;k++){
    float4 av = *(const float4*)(ApT + k*68);
    u64 a0=pack2(av.x,av.x), a1=pack2(av.y,av.y),
        a2=pack2(av.z,av.z), a3=pack2(av.w,av.w);
    u64 b2[NP2];
    const float4* b4 = (const float4*)(Bp + k*(BN+4));
#pragma unroll
    for (int j=0;j<NP2/2;j++){
      float4 t=b4[j];
      b2[2*j]=pack2(t.x,t.y); b2[2*j+1]=pack2(t.z,t.w);
    }
#pragma unroll
    for (int j=0;j<NP2;j++){
      fma2(acc[0][j],a0,b2[j]);
      fma2(acc[1][j],a1,b2[j]);
      fma2(acc[2][j],a2,b2[j]);
      fma2(acc[3][j],a3,b2[j]);
    }
  }

  float vals[4][NPT];
#pragma unroll
  for (int i=0;i<4;i++)
#pragma unroll
    for (int j=0;j<NP2;j++) unpack2(vals[i][2*j], vals[i][2*j+1], acc[i][j]);

  if (!POOL){
#pragma unroll
    for (int i=0;i<4;i++){
      float* outp = H + (size_t)(m0+tm*4+i)*BN + tn*NPT;
#pragma unroll
      for (int j=0;j<NPT/4;j++){
        float4 t; t.x=vals[i][4*j]; t.y=vals[i][4*j+1]; t.z=vals[i][4*j+2]; t.w=vals[i][4*j+3];
        *(float4*)(outp + 4*j) = t;
      }
    }
  }

  // ---- deterministic column sum / sumsq (as R5) ----
  __syncthreads();
  float* sS  = sm;                      // [BN][16]
  float* sSS = sm + 16*BN;              // [BN][16]
#pragma unroll
  for (int j=0;j<NPT;j++){
    float v0=vals[0][j], v1=vals[1][j], v2=vals[2][j], v3=vals[3][j];
    sS [(tn*NPT+j)*16 + tm] = ((v0+v1)+v2)+v3;
    sSS[(tn*NPT+j)*16 + tm] = ((v0*v0+v1*v1)+v2*v2)+v3*v3;
  }
  __syncthreads();
  if (tid < BN){
    float s=0.f, ss=0.f;
#pragma unroll
    for (int t=0;t<16;t++){ s+=sS[tid*16+t]; ss+=sSS[tid*16+t]; }
    g_pS [(size_t)tid*NBLK + blockIdx.x] = s;
    g_pSS[(size_t)tid*NBLK + blockIdx.x] = ss;
  }

  if (POOL){
    // rows tm*4..tm*4+3 all lie in sample group tm>>3 (32 rows per sample)
    __syncthreads();
#pragma unroll
    for (int j=0;j<NPT;j++){
      float mx = fmaxf(fmaxf(vals[0][j],vals[1][j]), fmaxf(vals[2][j],vals[3][j]));
      float mn = fminf(fminf(vals[0][j],vals[1][j]), fminf(vals[2][j],vals[3][j]));
      sS [(tn*NPT+j)*16 + tm] = mx;
      sSS[(tn*NPT+j)*16 + tm] = mn;
    }
    __syncthreads();
    // 256 threads -> (grp 0..1) x (col 0..127)
    {
      int grp = tid>>7, col = tid&127;
      float mx=-3.4e38f, mn=3.4e38f;
#pragma unroll
      for (int t=0;t<8;t++){
        mx = fmaxf(mx, sS [col*16 + grp*8 + t]);
        mn = fminf(mn, sSS[col*16 + grp*8 + t]);
      }
      size_t gidx = (size_t)(blockIdx.x*2+grp)*128 + col;
      g_mx[gidx]=mx; g_mn[gidx]=mn;
    }
  }
}

// ---------------- BN stats: one block per channel ---------------------------
__global__ void bnstats_kernel(const float* __restrict__ g, const float* __restrict__ beta){
  __shared__ float sh[512];
  const int c=blockIdx.x, t=threadIdx.x;   // 256 threads
  float s=0.f, ss=0.f;
  const float* ps  = g_pS  + (size_t)c*NBLK;
  const float* pss = g_pSS + (size_t)c*NBLK;
  for (int i=t;i<NBLK;i+=256){ s+=ps[i]; ss+=pss[i]; }
  sh[t]=s; sh[256+t]=ss; __syncthreads();
  for (int o=128;o>0;o>>=1){
    if (t<o){ sh[t]+=sh[t+o]; sh[256+t]+=sh[256+t+o]; }
    __syncthreads();
  }
  if (t==0){
    const float inv = 1.0f/(float)MROWS;
    float mean = sh[0]*inv;
    float var  = sh[256]*inv - mean*mean;
    float rstd = rsqrtf(var + 1e-5f);
    float sc   = rstd*g[c];
    g_scale[c] = sc;
    g_shift[c] = beta[c] - mean*sc;
  }
}

// ---------------- final pool: norm+relu on pre-reduced max/min -------------
__global__ void pool_kernel(float* __restrict__ out){
  const int gq=blockIdx.x;                   // 0..8191 (b*1024+s)
  const int o =threadIdx.x;                  // 0..127
  const int b=gq>>10, s=gq&1023;
  const float sc=g_scale[o], sh=g_shift[o];
  const float mx=g_mx[(size_t)gq*128+o], mn=g_mn[(size_t)gq*128+o];
  float v = (sc>=0.f)? fmaf(mx,sc,sh) : fmaf(mn,sc,sh);
  out[24576 + (size_t)b*131072 + (size_t)o*1024 + s] = fmaxf(v, 0.f);
}

// ---------------- launch ----------------------------------------------------
extern "C" void kernel_launch(void* const* d_in, const int* in_sizes, int n_in,
                              void* d_out, int out_size){
  (void)in_sizes; (void)n_in; (void)out_size;
  const float* xyz = (const float*)d_in[0];
  const float* pts = (const float*)d_in[1];
  const float* w0  = (const float*)d_in[2];
  const float* b0  = (const float*)d_in[3];
  const float* gg0 = (const float*)d_in[4];
  const float* be0 = (const float*)d_in[5];
  const float* w1  = (const float*)d_in[6];
  const float* b1  = (const float*)d_in[7];
  const float* gg1 = (const float*)d_in[8];
  const float* be1 = (const float*)d_in[9];
  const float* w2  = (const float*)d_in[10];
  const float* b2  = (const float*)d_in[11];
  const float* gg2 = (const float*)d_in[12];
  const float* be2 = (const float*)d_in[13];
  float* out = (float*)d_out;

  // smem sizes (floats): K*68 + K*(BN+4) + BN + 2*K (AFF)
  const int smem1 = (68*68 + 68*68 + 64)*4;           // 37248
  const int smem2 = (64*68 + 64*68 + 64  + 2*64)*4;   // 35584
  const int smem3 = (64*68 + 64*132+ 128 + 2*64)*4;   // 52224

  cudaFuncSetAttribute(fps_kernel, cudaFuncAttributeMaxDynamicSharedMemorySize, 3*NPTS*4);
  cudaFuncSetAttribute((const void*)gemm_kernel<68,64,0>,
                       cudaFuncAttributeMaxDynamicSharedMemorySize, smem1);
  cudaFuncSetAttribute((const void*)gemm_kernel<64,64,1>,
                       cudaFuncAttributeMaxDynamicSharedMemorySize, smem2);
  cudaFuncSetAttribute((const void*)gemm_kernel<64,128,2>,
                       cudaFuncAttributeMaxDynamicSharedMemorySize, smem3);

  float *pH1,*pH2;
  cudaGetSymbolAddress((void**)&pH1, g_h1);
  cudaGetSymbolAddress((void**)&pH2, g_h2);

  fps_kernel<<<BATCH, 1024, 3*NPTS*4>>>(xyz);
  newxyz_kernel<<<BATCH, SPTS>>>(xyz, out);
  ball_kernel<<<1024, 256>>>(xyz);
  transpose_kernel<<<dim3(NPTS/32, DIM/32, BATCH), dim3(32,8)>>>(pts);

  gemm_kernel<68,64,0><<<NBLK, 256, smem1>>>(nullptr, w0, 67, b0, pH1, xyz);
  bnstats_kernel<<<64, 256>>>(gg0, be0);

  gemm_kernel<64,64,1><<<NBLK, 256, smem2>>>(pH1, w1, 64, b1, pH2, xyz);
  bnstats_kernel<<<64, 256>>>(gg1, be1);

  gemm_kernel<64,128,2><<<NBLK, 256, smem3>>>(pH2, w2, 64, b2, nullptr, xyz);
  bnstats_kernel<<<128, 256>>>(gg2, be2);

  pool_kernel<<<BATCH*SPTS, 128>>>(out);
}